// round 5
// baseline (speedup 1.0000x reference)
#include <cuda_runtime.h>
#include <cstdint>

// Transducer KD loss prep — cp.async pipelined version.
// logits/teacher (N=8,T=200,U=50,V=500) fp32; y (N,U) i32; x_lens,y_lens (N,) i32.
// Output (2, N, T, U, 3) fp32.
//
// One warp per PAIR of (n,t,u) positions; each position = student row + teacher
// row (shared mask + y). Rows are staged into smem via cp.async.cg (L1-bypass,
// no register cost for MLP), two commit-groups deep:
//   issue p0 -> issue p1 -> wait 1 -> compute p0 -> wait 0 -> compute p1.

#define TN 8
#define TT 200
#define TU 50
#define TV 500
#define T_EPS 1e-10f
#define NEG_BIG -1e30f

#define WARPS_PER_BLOCK 4
#define ROW_STRIDE 512   // floats; 500 data + pad (2048 B, 16B aligned)

__device__ __forceinline__ void cp16(uint32_t smem_addr, const void* gptr) {
    asm volatile("cp.async.cg.shared.global [%0], [%1], 16;\n"
                 :: "r"(smem_addr), "l"(gptr));
}

__global__ void __launch_bounds__(WARPS_PER_BLOCK * 32)
transducer_kd_kernel(const float* __restrict__ logits,
                     const float* __restrict__ teacher,
                     const int*   __restrict__ y,
                     const int*   __restrict__ x_lens,
                     const int*   __restrict__ y_lens,
                     float*       __restrict__ out)
{
    // [warp][pos(2)][tensor(2)][ROW_STRIDE]
    __shared__ __align__(16) float buf[WARPS_PER_BLOCK][2][2][ROW_STRIDE];

    const int warp_in_blk = threadIdx.x >> 5;
    const int lane = threadIdx.x & 31;
    const int pair = blockIdx.x * WARPS_PER_BLOCK + warp_in_blk;

    const int ROWS = TN * TT * TU;            // 80000 positions
    const int PAIRS = ROWS / 2;               // 40000
    if (pair >= PAIRS) return;

    const bool tail = (lane < 29);            // 125 float4 per row

    int  p[2];
    bool act[2];
    int  nn[2], uu[2];
    #pragma unroll
    for (int i = 0; i < 2; i++) {
        const int r  = pair * 2 + i;
        p[i] = r;
        const int n  = r / (TT * TU);
        const int tu = r - n * (TT * TU);
        const int t  = tu / TU;
        const int u  = tu - t * TU;
        nn[i] = n; uu[i] = u;
        act[i] = (t < x_lens[n]) && (u < y_lens[n]);
    }

    // ---- Issue phase: 2 commit groups, up to 16 cp.asyncs per lane ----
    #pragma unroll
    for (int i = 0; i < 2; i++) {
        if (act[i]) {
            const float* sg = logits  + (size_t)p[i] * TV;
            const float* tg = teacher + (size_t)p[i] * TV;
            uint32_t ss = (uint32_t)__cvta_generic_to_shared(&buf[warp_in_blk][i][0][0]);
            uint32_t ts = (uint32_t)__cvta_generic_to_shared(&buf[warp_in_blk][i][1][0]);
            cp16(ss + (lane      ) * 16, sg + (lane      ) * 4);
            cp16(ss + (lane + 32 ) * 16, sg + (lane + 32 ) * 4);
            cp16(ss + (lane + 64 ) * 16, sg + (lane + 64 ) * 4);
            cp16(ts + (lane      ) * 16, tg + (lane      ) * 4);
            cp16(ts + (lane + 32 ) * 16, tg + (lane + 32 ) * 4);
            cp16(ts + (lane + 64 ) * 16, tg + (lane + 64 ) * 4);
            if (tail) {
                cp16(ss + (lane + 96) * 16, sg + (lane + 96) * 4);
                cp16(ts + (lane + 96) * 16, tg + (lane + 96) * 4);
            }
        }
        asm volatile("cp.async.commit_group;\n" ::: "memory");
    }

    // ---- Compute phase ----
    #pragma unroll
    for (int i = 0; i < 2; i++) {
        float* os = out + (size_t)p[i] * 3;
        float* ot = out + (size_t)(ROWS + p[i]) * 3;

        if (i == 0) {
            asm volatile("cp.async.wait_group 1;\n" ::: "memory");
        } else {
            asm volatile("cp.async.wait_group 0;\n" ::: "memory");
        }
        __syncwarp();

        if (!act[i]) {
            if (lane < 3) { os[lane] = 0.0f; ot[lane] = 0.0f; }
            continue;
        }

        const float* sbuf = &buf[warp_in_blk][i][0][0];
        const float* tbuf = &buf[warp_in_blk][i][1][0];
        const float4* s4 = (const float4*)sbuf;
        const float4* t4 = (const float4*)tbuf;

        float4 sv0 = s4[lane];
        float4 sv1 = s4[lane + 32];
        float4 sv2 = s4[lane + 64];
        float4 tv0 = t4[lane];
        float4 tv1 = t4[lane + 32];
        float4 tv2 = t4[lane + 64];
        float4 sv3 = make_float4(NEG_BIG, NEG_BIG, NEG_BIG, NEG_BIG);
        float4 tv3 = make_float4(NEG_BIG, NEG_BIG, NEG_BIG, NEG_BIG);
        if (tail) { sv3 = s4[lane + 96]; tv3 = t4[lane + 96]; }

        float sa = (__expf(sv0.x) + __expf(sv0.y)) + (__expf(sv0.z) + __expf(sv0.w));
        sa += (__expf(sv1.x) + __expf(sv1.y)) + (__expf(sv1.z) + __expf(sv1.w));
        sa += (__expf(sv2.x) + __expf(sv2.y)) + (__expf(sv2.z) + __expf(sv2.w));
        sa += (__expf(sv3.x) + __expf(sv3.y)) + (__expf(sv3.z) + __expf(sv3.w));
        float ta = (__expf(tv0.x) + __expf(tv0.y)) + (__expf(tv0.z) + __expf(tv0.w));
        ta += (__expf(tv1.x) + __expf(tv1.y)) + (__expf(tv1.z) + __expf(tv1.w));
        ta += (__expf(tv2.x) + __expf(tv2.y)) + (__expf(tv2.z) + __expf(tv2.w));
        ta += (__expf(tv3.x) + __expf(tv3.y)) + (__expf(tv3.z) + __expf(tv3.w));

        #pragma unroll
        for (int off = 16; off > 0; off >>= 1) {
            sa += __shfl_xor_sync(0xFFFFFFFFu, sa, off);
            ta += __shfl_xor_sync(0xFFFFFFFFu, ta, off);
        }

        if (lane == 0) {
            const int yi = __ldg(y + nn[i] * TU + uu[i]);
            const float s_ly = sbuf[yi];
            const float t_ly = tbuf[yi];
            const float s_lb = sbuf[0];
            const float t_lb = tbuf[0];

            const float sinv   = 1.0f / sa;
            const float spy    = __expf(s_ly) * sinv;
            const float sblank = __expf(s_lb) * sinv;
            const float srem   = 1.0f - spy - sblank;
            os[0] = logf(fminf(fmaxf(spy,    T_EPS), 1.0f));
            os[1] = logf(fminf(fmaxf(sblank, T_EPS), 1.0f));
            os[2] = logf(fminf(fmaxf(srem,   T_EPS), 1.0f));

            const float tinv   = 1.0f / ta;
            const float tpy    = __expf(t_ly) * tinv;
            const float tblank = __expf(t_lb) * tinv;
            const float trem   = 1.0f - tpy - tblank;
            ot[0] = tpy;
            ot[1] = tblank;
            ot[2] = (trem < 0.0f) ? T_EPS : trem;
        }
    }
}

extern "C" void kernel_launch(void* const* d_in, const int* in_sizes, int n_in,
                              void* d_out, int out_size)
{
    const float* logits  = (const float*)d_in[0];
    const float* teacher = (const float*)d_in[1];
    const int*   y       = (const int*)d_in[2];
    const int*   x_lens  = (const int*)d_in[3];
    const int*   y_lens  = (const int*)d_in[4];
    float* out = (float*)d_out;

    const int PAIRS = (TN * TT * TU) / 2;   // 40000
    const int blocks = (PAIRS + WARPS_PER_BLOCK - 1) / WARPS_PER_BLOCK;
    transducer_kd_kernel<<<blocks, WARPS_PER_BLOCK * 32>>>(
        logits, teacher, y, x_lens, y_lens, out);
}

// round 6
// speedup vs baseline: 1.3026x; 1.3026x over previous
#include <cuda_runtime.h>
#include <cstdint>

// Transducer KD loss prep — PERSISTENT cp.async pipelined kernel.
// logits/teacher (N=8,T=200,U=50,V=500) fp32; y (N,U) i32; x_lens,y_lens (N,) i32.
// Output (2, N, T, U, 3) fp32.
//
// Grid-stride persistent warps. Each warp owns a private 2-stage smem ring
// (stage = one (n,t,u) position = student row + teacher row = 4000B).
// Steady state:  issue(p+S) -> commit -> wait_group 1 -> compute(p).
// cp.async.cg keeps 4KB/warp perpetually in flight with zero register cost,
// decoupling MLP from occupancy (the R2-R4 plateau).

#define TN 8
#define TT 200
#define TU 50
#define TV 500
#define ROWS (TN * TT * TU)          // 80000 positions
#define T_EPS 1e-10f
#define NEG_BIG -1e30f

#define WARPS_PER_BLOCK 4
#define NBLOCKS (148 * 7)            // 1036 persistent blocks
#define TOTAL_WARPS (NBLOCKS * WARPS_PER_BLOCK)   // 4144
#define STAGE_FLOATS (2 * TV)        // 1000 floats = 4000B per stage

struct Pos { int p, n, u; bool act; };

__device__ __forceinline__ void cp16(uint32_t smem_addr, const float* gptr) {
    asm volatile("cp.async.cg.shared.global [%0], [%1], 16;\n"
                 :: "r"(smem_addr), "l"(gptr));
}

__device__ __forceinline__ Pos decode(int p, const int* __restrict__ xl,
                                      const int* __restrict__ yl) {
    Pos q;
    q.p = p;
    const int n  = p / (TT * TU);
    const int tu = p - n * (TT * TU);
    const int t  = tu / TU;
    const int u  = tu - t * TU;
    q.n = n; q.u = u;
    q.act = (t < __ldg(xl + n)) && (u < __ldg(yl + n));
    return q;
}

__global__ void __launch_bounds__(WARPS_PER_BLOCK * 32)
transducer_kd_kernel(const float* __restrict__ logits,
                     const float* __restrict__ teacher,
                     const int*   __restrict__ y,
                     const int*   __restrict__ x_lens,
                     const int*   __restrict__ y_lens,
                     float*       __restrict__ out)
{
    // [warp][stage][2 rows * 500 floats]  = 4*2*1000*4 = 32000 B
    __shared__ __align__(16) float buf[WARPS_PER_BLOCK][2][STAGE_FLOATS];

    const int w    = threadIdx.x >> 5;
    const int lane = threadIdx.x & 31;
    const int gw   = blockIdx.x * WARPS_PER_BLOCK + w;
    const bool tail = (lane < 29);           // 125 float4 per row

    // ---- issue one position into a stage ----
    auto issue = [&](const Pos& q, int s) {
        if (!q.act) return;
        const float* sg = logits  + (size_t)q.p * TV;
        const float* tg = teacher + (size_t)q.p * TV;
        uint32_t sb = (uint32_t)__cvta_generic_to_shared(&buf[w][s][0]);
        uint32_t tb = sb + TV * 4;           // teacher row at +2000B
        cp16(sb + (lane      ) * 16, sg + (lane      ) * 4);
        cp16(sb + (lane + 32 ) * 16, sg + (lane + 32 ) * 4);
        cp16(sb + (lane + 64 ) * 16, sg + (lane + 64 ) * 4);
        cp16(tb + (lane      ) * 16, tg + (lane      ) * 4);
        cp16(tb + (lane + 32 ) * 16, tg + (lane + 32 ) * 4);
        cp16(tb + (lane + 64 ) * 16, tg + (lane + 64 ) * 4);
        if (tail) {
            cp16(sb + (lane + 96) * 16, sg + (lane + 96) * 4);
            cp16(tb + (lane + 96) * 16, tg + (lane + 96) * 4);
        }
    };

    // ---- compute one staged position ----
    auto compute = [&](const Pos& q, int s) {
        float* os = out + (size_t)q.p * 3;
        float* ot = out + (size_t)(ROWS + q.p) * 3;
        if (!q.act) {
            if (lane < 3) { os[lane] = 0.0f; ot[lane] = 0.0f; }
            return;
        }
        const float*  sbuf = &buf[w][s][0];
        const float*  tbuf = sbuf + TV;
        const float4* s4 = (const float4*)sbuf;
        const float4* t4 = (const float4*)tbuf;

        float4 sv0 = s4[lane];
        float4 sv1 = s4[lane + 32];
        float4 sv2 = s4[lane + 64];
        float4 tv0 = t4[lane];
        float4 tv1 = t4[lane + 32];
        float4 tv2 = t4[lane + 64];
        float4 sv3 = make_float4(NEG_BIG, NEG_BIG, NEG_BIG, NEG_BIG);
        float4 tv3 = make_float4(NEG_BIG, NEG_BIG, NEG_BIG, NEG_BIG);
        if (tail) { sv3 = s4[lane + 96]; tv3 = t4[lane + 96]; }

        float sa = (__expf(sv0.x) + __expf(sv0.y)) + (__expf(sv0.z) + __expf(sv0.w));
        sa += (__expf(sv1.x) + __expf(sv1.y)) + (__expf(sv1.z) + __expf(sv1.w));
        sa += (__expf(sv2.x) + __expf(sv2.y)) + (__expf(sv2.z) + __expf(sv2.w));
        sa += (__expf(sv3.x) + __expf(sv3.y)) + (__expf(sv3.z) + __expf(sv3.w));
        float ta = (__expf(tv0.x) + __expf(tv0.y)) + (__expf(tv0.z) + __expf(tv0.w));
        ta += (__expf(tv1.x) + __expf(tv1.y)) + (__expf(tv1.z) + __expf(tv1.w));
        ta += (__expf(tv2.x) + __expf(tv2.y)) + (__expf(tv2.z) + __expf(tv2.w));
        ta += (__expf(tv3.x) + __expf(tv3.y)) + (__expf(tv3.z) + __expf(tv3.w));

        #pragma unroll
        for (int off = 16; off > 0; off >>= 1) {
            sa += __shfl_xor_sync(0xFFFFFFFFu, sa, off);
            ta += __shfl_xor_sync(0xFFFFFFFFu, ta, off);
        }

        if (lane == 0) {
            const int yi = __ldg(y + q.n * TU + q.u);
            const float s_ly = sbuf[yi];
            const float t_ly = tbuf[yi];
            const float s_lb = sbuf[0];
            const float t_lb = tbuf[0];

            const float sinv   = 1.0f / sa;
            const float spy    = __expf(s_ly) * sinv;
            const float sblank = __expf(s_lb) * sinv;
            const float srem   = 1.0f - spy - sblank;
            os[0] = logf(fminf(fmaxf(spy,    T_EPS), 1.0f));
            os[1] = logf(fminf(fmaxf(sblank, T_EPS), 1.0f));
            os[2] = logf(fminf(fmaxf(srem,   T_EPS), 1.0f));

            const float tinv   = 1.0f / ta;
            const float tpy    = __expf(t_ly) * tinv;
            const float tblank = __expf(t_lb) * tinv;
            const float trem   = 1.0f - tpy - tblank;
            ot[0] = tpy;
            ot[1] = tblank;
            ot[2] = (trem < 0.0f) ? T_EPS : trem;
        }
    };

    // ---- persistent pipelined main loop ----
    if (gw >= ROWS) return;

    Pos cur = decode(gw, x_lens, y_lens);
    issue(cur, 0);
    asm volatile("cp.async.commit_group;\n" ::: "memory");

    int stage = 0;
    for (int p = gw; p < ROWS; p += TOTAL_WARPS) {
        const int pn = p + TOTAL_WARPS;
        Pos nxt; nxt.act = false; nxt.p = 0; nxt.n = 0; nxt.u = 0;
        if (pn < ROWS) {
            nxt = decode(pn, x_lens, y_lens);
            issue(nxt, stage ^ 1);
        }
        asm volatile("cp.async.commit_group;\n" ::: "memory");
        asm volatile("cp.async.wait_group 1;\n" ::: "memory");
        __syncwarp();

        compute(cur, stage);
        cur = nxt;
        stage ^= 1;
    }
}

extern "C" void kernel_launch(void* const* d_in, const int* in_sizes, int n_in,
                              void* d_out, int out_size)
{
    const float* logits  = (const float*)d_in[0];
    const float* teacher = (const float*)d_in[1];
    const int*   y       = (const int*)d_in[2];
    const int*   x_lens  = (const int*)d_in[3];
    const int*   y_lens  = (const int*)d_in[4];
    float* out = (float*)d_out;

    transducer_kd_kernel<<<NBLOCKS, WARPS_PER_BLOCK * 32>>>(
        logits, teacher, y, x_lens, y_lens, out);
}